// round 9
// baseline (speedup 1.0000x reference)
#include <cuda_runtime.h>
#include <cuda_fp16.h>
#include <math.h>
#include <stdint.h>

#define DM    1024
#define FFN_  4096
#define NE    8
#define TMAX  8192
#define GROWS (2*TMAX + 128)

// ---------------- device scratch ----------------
__device__ int    g_counts[NE];
__device__ int    g_base[NE];
__device__ int    g_tok[NE][TMAX];
__device__ int    g_texp[TMAX][2];
__device__ int    g_tslot[TMAX][2];
__device__ float  g_tgate[TMAX][2];
__device__ __half g_Xgh[(size_t)GROWS * DM];
__device__ __half g_Hh[(size_t)GROWS * FFN_];
__device__ float  g_Y[(size_t)GROWS * DM];
__device__ __half g_w1h[(size_t)NE * DM * FFN_];
__device__ __half g_w2h[(size_t)NE * FFN_ * DM];

// ---------------- helpers ----------------
__device__ __forceinline__ uint32_t smem_u32(const void* p) {
    uint32_t a;
    asm("{ .reg .u64 t; cvta.to.shared.u64 t, %1; cvt.u32.u64 %0, t; }" : "=r"(a) : "l"(p));
    return a;
}
__device__ __forceinline__ float gelu_exact(float v) {
    return 0.5f * v * (1.f + erff(v * 0.7071067811865476f));
}

#define CP_ASYNC16(dst, src) \
    asm volatile("cp.async.cg.shared.global [%0], [%1], 16;" :: "r"(dst), "l"(src) : "memory")
#define CP_COMMIT()  asm volatile("cp.async.commit_group;" ::: "memory")
#define CP_WAIT1()   asm volatile("cp.async.wait_group 1;" ::: "memory")

#define LDMATRIX_X4(r0,r1,r2,r3, addr) \
    asm volatile("ldmatrix.sync.aligned.m8n8.x4.shared.b16 {%0,%1,%2,%3}, [%4];" \
        : "=r"(r0), "=r"(r1), "=r"(r2), "=r"(r3) : "r"(addr))
#define LDMATRIX_X4_T(r0,r1,r2,r3, addr) \
    asm volatile("ldmatrix.sync.aligned.m8n8.x4.trans.shared.b16 {%0,%1,%2,%3}, [%4];" \
        : "=r"(r0), "=r"(r1), "=r"(r2), "=r"(r3) : "r"(addr))

#define MMA_F16(c, a, b0, b1) \
    asm volatile("mma.sync.aligned.m16n8k16.row.col.f32.f16.f16.f32 " \
        "{%0,%1,%2,%3}, {%4,%5,%6,%7}, {%8,%9}, {%0,%1,%2,%3};" \
        : "+f"((c)[0]), "+f"((c)[1]), "+f"((c)[2]), "+f"((c)[3]) \
        : "r"((a)[0]), "r"((a)[1]), "r"((a)[2]), "r"((a)[3]), "r"(b0), "r"(b1))

// ---------------- routing ----------------
__global__ void init_kernel() { if (threadIdx.x < NE) g_counts[threadIdx.x] = 0; }

__global__ void base_kernel() {
    if (threadIdx.x == 0) {
        int s = 0;
        #pragma unroll
        for (int e = 0; e < NE; e++) { g_base[e] = s; s += g_counts[e]; }
    }
}

__global__ void route_kernel(const float* __restrict__ x,
                             const float* __restrict__ gw,
                             const float* __restrict__ gb, int T) {
    int warp = (blockIdx.x * blockDim.x + threadIdx.x) >> 5;
    int lane = threadIdx.x & 31;
    if (warp >= T) return;
    const float* xr = x + (size_t)warp * DM;
    float acc[NE];
    #pragma unroll
    for (int e = 0; e < NE; e++) acc[e] = 0.f;
    for (int d = lane; d < DM; d += 32) {
        float xv = xr[d];
        const float4* g4 = (const float4*)(gw + (size_t)d * NE);
        float4 a = g4[0], b = g4[1];
        acc[0] += xv*a.x; acc[1] += xv*a.y; acc[2] += xv*a.z; acc[3] += xv*a.w;
        acc[4] += xv*b.x; acc[5] += xv*b.y; acc[6] += xv*b.z; acc[7] += xv*b.w;
    }
    #pragma unroll
    for (int e = 0; e < NE; e++)
        #pragma unroll
        for (int o = 16; o > 0; o >>= 1) acc[e] += __shfl_xor_sync(0xFFFFFFFFu, acc[e], o);
    if (lane == 0) {
        float v[NE];
        #pragma unroll
        for (int e = 0; e < NE; e++) v[e] = acc[e] + gb[e];
        int i1 = 0;
        #pragma unroll
        for (int e = 1; e < NE; e++) if (v[e] > v[i1]) i1 = e;
        int i2 = (i1 == 0) ? 1 : 0;
        #pragma unroll
        for (int e = 0; e < NE; e++) if (e != i1 && v[e] > v[i2]) i2 = e;
        float e2 = expf(v[i2] - v[i1]);
        float s = 1.f + e2;
        int s1 = atomicAdd(&g_counts[i1], 1);
        g_tok[i1][s1] = warp;
        int s2 = atomicAdd(&g_counts[i2], 1);
        g_tok[i2][s2] = warp;
        g_texp[warp][0] = i1; g_tslot[warp][0] = s1; g_tgate[warp][0] = 1.f / s;
        g_texp[warp][1] = i2; g_tslot[warp][1] = s2; g_tgate[warp][1] = e2 / s;
    }
}

__global__ void gather_kernel(const float* __restrict__ x) {
    int e = blockIdx.y;
    int slot = blockIdx.x * 2 + (threadIdx.x >> 7);
    if (slot >= g_counts[e]) return;
    int tok = g_tok[e][slot];
    int row = g_base[e] + slot;
    int lane = threadIdx.x & 127;
    const float4* s = (const float4*)(x + (size_t)tok * DM);
    uint2* d = (uint2*)(g_Xgh + (size_t)row * DM);
    #pragma unroll
    for (int i = 0; i < 2; i++) {
        float4 v = s[lane + i * 128];
        __half2 h0 = __floats2half2_rn(v.x, v.y);
        __half2 h1 = __floats2half2_rn(v.z, v.w);
        uint2 o;
        o.x = *reinterpret_cast<uint32_t*>(&h0);
        o.y = *reinterpret_cast<uint32_t*>(&h1);
        d[lane + i * 128] = o;
    }
}

// combine: out[tok] = g0*Y[row0] + g1*Y[row1]
__global__ void combine_kernel(float* __restrict__ out, int T) {
    int tok = blockIdx.x * 2 + (threadIdx.x >> 7);
    if (tok >= T) return;
    int lane = threadIdx.x & 127;
    int r0 = g_base[g_texp[tok][0]] + g_tslot[tok][0];
    int r1 = g_base[g_texp[tok][1]] + g_tslot[tok][1];
    float g0 = g_tgate[tok][0], g1 = g_tgate[tok][1];
    const float4* y0 = (const float4*)(g_Y + (size_t)r0 * DM);
    const float4* y1 = (const float4*)(g_Y + (size_t)r1 * DM);
    float4* d = (float4*)(out + (size_t)tok * DM);
    #pragma unroll
    for (int i = 0; i < 2; i++) {
        float4 a = y0[lane + i * 128];
        float4 b = y1[lane + i * 128];
        float4 o;
        o.x = g0 * a.x + g1 * b.x;
        o.y = g0 * a.y + g1 * b.y;
        o.z = g0 * a.z + g1 * b.z;
        o.w = g0 * a.w + g1 * b.w;
        d[lane + i * 128] = o;
    }
}

// fp32 -> fp16 conversion of BOTH weight tensors in one launch
__global__ void conv_half_kernel(const float4* __restrict__ s1, uint4* __restrict__ d1,
                                 const float4* __restrict__ s2, uint4* __restrict__ d2, int n8) {
    int i = blockIdx.x * blockDim.x + threadIdx.x;
    if (i >= 2 * n8) return;
    const float4* s = (i < n8) ? s1 : s2;
    uint4* d = (i < n8) ? d1 : d2;
    int j = (i < n8) ? i : (i - n8);
    float4 v0 = s[j * 2], v1 = s[j * 2 + 1];
    __half2 h0 = __floats2half2_rn(v0.x, v0.y);
    __half2 h1 = __floats2half2_rn(v0.z, v0.w);
    __half2 h2 = __floats2half2_rn(v1.x, v1.y);
    __half2 h3 = __floats2half2_rn(v1.z, v1.w);
    uint4 o;
    o.x = *reinterpret_cast<uint32_t*>(&h0);
    o.y = *reinterpret_cast<uint32_t*>(&h1);
    o.z = *reinterpret_cast<uint32_t*>(&h2);
    o.w = *reinterpret_cast<uint32_t*>(&h3);
    d[j] = o;
}

// ---------------- fp16 mma grouped GEMM ----------------
// CTA 128x128, 256 threads = 8 warps (2x4), warp tile 64x32, k-chunk 64.
// smem (halves): A [128][72], B [64][136], 3-stage pipeline.
#define ASTRH 72
#define BSTRH 136
#define ABUFB (128 * ASTRH * 2)          // 18432 B
#define BBUFB (64 * BSTRH * 2)           // 17408 B
#define BUFB  (ABUFB + BBUFB)            // 35840 B
#define NSTAGE 3
#define SMEM_DYN (NSTAGE * BUFB)         // 107520 B

template<int KDIM, int NDIM, bool GELU_OUT>
__global__ void __launch_bounds__(256, 2)
gemm_mma(const __half* __restrict__ Bmat, const float* __restrict__ bias) {
    const int e = blockIdx.z;
    const int count = g_counts[e];
    const int m0 = blockIdx.x * 128;
    if (m0 >= count) return;
    const int base = g_base[e];
    const int n0 = blockIdx.y * 128;

    extern __shared__ char smraw[];
    const uint32_t su = smem_u32(smraw);

    const int tid  = threadIdx.x;
    const int wid  = tid >> 5;
    const int lane = tid & 31;
    const int g    = lane >> 2;
    const int tg   = lane & 3;
    const int wr   = wid & 1;
    const int wc   = wid >> 1;

    const __half* Asrc = (GELU_OUT ? g_Xgh : g_Hh) + (size_t)(base + m0) * KDIM;
    const __half* Bsrc = Bmat + (size_t)e * KDIM * NDIM + n0;

    // loader mapping: A rows 0..127, 2 threads/row, 4 x 16B each
    const int am = tid >> 1;
    const int ac = (tid & 1) * 4;
    // B rows 0..63, 4 threads/row, 4 x 16B each
    const int bk = tid >> 2;
    const int bc = (tid & 3) * 4;

    const int lane_r  = (lane & 7) + ((lane >> 3) & 1) * 8;
    const int lane_k8 = (lane >> 4) * 16;

    float c[4][4][4];
    #pragma unroll
    for (int i = 0; i < 4; i++)
        #pragma unroll
        for (int j = 0; j < 4; j++)
            #pragma unroll
            for (int k = 0; k < 4; k++) c[i][j][k] = 0.f;

    const int KC = KDIM / 64;

    #define LOAD_TILES(kc_, buf_) do { \
        uint32_t sa = su + (buf_) * BUFB; \
        uint32_t sb = sa + ABUFB; \
        const __half* asp = Asrc + (size_t)am * KDIM + (kc_) * 64; \
        _Pragma("unroll") \
        for (int j = 0; j < 4; j++) \
            CP_ASYNC16(sa + (uint32_t)(am * 144 + (ac + j) * 16), asp + (ac + j) * 8); \
        const __half* bsp = Bsrc + (size_t)((kc_) * 64 + bk) * NDIM; \
        _Pragma("unroll") \
        for (int j = 0; j < 4; j++) \
            CP_ASYNC16(sb + (uint32_t)(bk * 272 + (bc + j) * 16), bsp + (bc + j) * 8); \
    } while (0)

    LOAD_TILES(0, 0); CP_COMMIT();
    LOAD_TILES(1, 1); CP_COMMIT();

    int buf = 0;
    int lbuf = 2;
    for (int kc = 0; kc < KC; kc++) {
        CP_WAIT1();
        __syncthreads();
        if (kc + 2 < KC) LOAD_TILES(kc + 2, lbuf);
        CP_COMMIT();
        if (++lbuf == NSTAGE) lbuf = 0;

        const uint32_t sa = su + buf * BUFB;
        const uint32_t sb = sa + ABUFB;
        if (++buf == NSTAGE) buf = 0;
        const uint32_t a_base = sa + (uint32_t)((wr * 64 + lane_r) * 144) + lane_k8;
        const uint32_t b_base = sb + (uint32_t)(lane_r * 272 + wc * 64) + lane_k8;

        #pragma unroll
        for (int ks = 0; ks < 4; ks++) {
            uint32_t a[4][4];
            #pragma unroll
            for (int mf = 0; mf < 4; mf++)
                LDMATRIX_X4(a[mf][0], a[mf][1], a[mf][2], a[mf][3],
                            a_base + mf * 2304 + ks * 32);
            uint32_t b[4][2];
            #pragma unroll
            for (int np = 0; np < 2; np++) {
                uint32_t r0, r1, r2, r3;
                LDMATRIX_X4_T(r0, r1, r2, r3, b_base + ks * 4352 + np * 32);
                b[np * 2 + 0][0] = r0; b[np * 2 + 0][1] = r1;
                b[np * 2 + 1][0] = r2; b[np * 2 + 1][1] = r3;
            }
            #pragma unroll
            for (int mf = 0; mf < 4; mf++)
                #pragma unroll
                for (int nf = 0; nf < 4; nf++)
                    MMA_F16(c[mf][nf], a[mf], b[nf][0], b[nf][1]);
        }
    }

    // -------- epilogue --------
    #pragma unroll
    for (int mf = 0; mf < 4; mf++) {
        #pragma unroll
        for (int half_ = 0; half_ < 2; half_++) {
            int rl = wr * 64 + mf * 16 + g + half_ * 8;
            int m = m0 + rl;
            if (m >= count) continue;
            if (GELU_OUT) {
                __half* hrow = g_Hh + (size_t)(base + m) * FFN_;
                #pragma unroll
                for (int nf = 0; nf < 4; nf++) {
                    int col = n0 + wc * 32 + nf * 8 + 2 * tg;
                    float2 bb = *(const float2*)(bias + (size_t)e * NDIM + col);
                    __half2 hv = __floats2half2_rn(
                        gelu_exact(c[mf][nf][half_ * 2 + 0] + bb.x),
                        gelu_exact(c[mf][nf][half_ * 2 + 1] + bb.y));
                    *reinterpret_cast<__half2*>(hrow + col) = hv;
                }
            } else {
                float* yrow = g_Y + (size_t)(base + m) * DM;
                #pragma unroll
                for (int nf = 0; nf < 4; nf++) {
                    int col = n0 + wc * 32 + nf * 8 + 2 * tg;
                    float2 bb = *(const float2*)(bias + (size_t)e * NDIM + col);
                    float2 v;
                    v.x = c[mf][nf][half_ * 2 + 0] + bb.x;
                    v.y = c[mf][nf][half_ * 2 + 1] + bb.y;
                    *(float2*)(yrow + col) = v;
                }
            }
        }
    }
}

// ---------------- launch ----------------
extern "C" void kernel_launch(void* const* d_in, const int* in_sizes, int n_in,
                              void* d_out, int out_size) {
    const float* x  = (const float*)d_in[0];
    const float* gw = (const float*)d_in[1];
    const float* gb = (const float*)d_in[2];
    const float* w1 = (const float*)d_in[3];
    const float* b1 = (const float*)d_in[4];
    const float* w2 = (const float*)d_in[5];
    const float* b2 = (const float*)d_in[6];
    float* out = (float*)d_out;
    const int T = in_sizes[0] / DM;

    __half* w1h; cudaGetSymbolAddress((void**)&w1h, g_w1h);
    __half* w2h; cudaGetSymbolAddress((void**)&w2h, g_w2h);

    static int attr_done = 0;
    if (!attr_done) {
        cudaFuncSetAttribute(gemm_mma<DM, FFN_, true>,
                             cudaFuncAttributeMaxDynamicSharedMemorySize, SMEM_DYN);
        cudaFuncSetAttribute(gemm_mma<FFN_, DM, false>,
                             cudaFuncAttributeMaxDynamicSharedMemorySize, SMEM_DYN);
        attr_done = 1;
    }

    init_kernel<<<1, 32>>>();
    route_kernel<<<(T + 7) / 8, 256>>>(x, gw, gb, T);
    base_kernel<<<1, 32>>>();
    gather_kernel<<<dim3((T + 1) / 2, NE), 256>>>(x);

    const int n8 = NE * DM * FFN_ / 8;
    conv_half_kernel<<<(2 * n8 + 255) / 256, 256>>>(
        (const float4*)w1, (uint4*)w1h, (const float4*)w2, (uint4*)w2h, n8);

    gemm_mma<DM, FFN_, true><<<dim3(T / 128, FFN_ / 128, NE), 256, SMEM_DYN>>>(w1h, b1);
    gemm_mma<FFN_, DM, false><<<dim3(T / 128, DM / 128, NE), 256, SMEM_DYN>>>(w2h, b2);

    combine_kernel<<<(T + 1) / 2, 256>>>(out, T);
}

// round 10
// speedup vs baseline: 1.2014x; 1.2014x over previous
#include <cuda_runtime.h>
#include <cuda_fp16.h>
#include <math.h>
#include <stdint.h>

#define DM    1024
#define FFN_  4096
#define NE    8
#define TMAX  8192
#define GROWS (2*TMAX + 128)

// ---------------- device scratch ----------------
__device__ int    g_counts[NE];
__device__ int    g_base[NE];
__device__ int    g_tok[NE][TMAX];
__device__ float  g_gate[NE][TMAX];
__device__ __half g_Xgh[(size_t)GROWS * DM];
__device__ __half g_Hh[(size_t)GROWS * FFN_];
__device__ __half g_w1h[(size_t)NE * DM * FFN_];
__device__ __half g_w2h[(size_t)NE * FFN_ * DM];

// ---------------- helpers ----------------
__device__ __forceinline__ uint32_t smem_u32(const void* p) {
    uint32_t a;
    asm("{ .reg .u64 t; cvta.to.shared.u64 t, %1; cvt.u32.u64 %0, t; }" : "=r"(a) : "l"(p));
    return a;
}
__device__ __forceinline__ float gelu_exact(float v) {
    return 0.5f * v * (1.f + erff(v * 0.7071067811865476f));
}

#define CP_ASYNC16(dst, src) \
    asm volatile("cp.async.cg.shared.global [%0], [%1], 16;" :: "r"(dst), "l"(src) : "memory")
#define CP_COMMIT()  asm volatile("cp.async.commit_group;" ::: "memory")
#define CP_WAIT2()   asm volatile("cp.async.wait_group 2;" ::: "memory")

#define LDMATRIX_X4(r0,r1,r2,r3, addr) \
    asm volatile("ldmatrix.sync.aligned.m8n8.x4.shared.b16 {%0,%1,%2,%3}, [%4];" \
        : "=r"(r0), "=r"(r1), "=r"(r2), "=r"(r3) : "r"(addr))
#define LDMATRIX_X4_T(r0,r1,r2,r3, addr) \
    asm volatile("ldmatrix.sync.aligned.m8n8.x4.trans.shared.b16 {%0,%1,%2,%3}, [%4];" \
        : "=r"(r0), "=r"(r1), "=r"(r2), "=r"(r3) : "r"(addr))

#define MMA_F16(c, a, b0, b1) \
    asm volatile("mma.sync.aligned.m16n8k16.row.col.f32.f16.f16.f32 " \
        "{%0,%1,%2,%3}, {%4,%5,%6,%7}, {%8,%9}, {%0,%1,%2,%3};" \
        : "+f"((c)[0]), "+f"((c)[1]), "+f"((c)[2]), "+f"((c)[3]) \
        : "r"((a)[0]), "r"((a)[1]), "r"((a)[2]), "r"((a)[3]), "r"(b0), "r"(b1))

// ---------------- routing ----------------
__global__ void init_kernel() { if (threadIdx.x < NE) g_counts[threadIdx.x] = 0; }

__global__ void base_kernel() {
    if (threadIdx.x == 0) {
        int s = 0;
        #pragma unroll
        for (int e = 0; e < NE; e++) { g_base[e] = s; s += g_counts[e]; }
    }
}

__global__ void route_kernel(const float* __restrict__ x,
                             const float* __restrict__ gw,
                             const float* __restrict__ gb, int T) {
    int warp = (blockIdx.x * blockDim.x + threadIdx.x) >> 5;
    int lane = threadIdx.x & 31;
    if (warp >= T) return;
    const float* xr = x + (size_t)warp * DM;
    float acc[NE];
    #pragma unroll
    for (int e = 0; e < NE; e++) acc[e] = 0.f;
    for (int d = lane; d < DM; d += 32) {
        float xv = xr[d];
        const float4* g4 = (const float4*)(gw + (size_t)d * NE);
        float4 a = g4[0], b = g4[1];
        acc[0] += xv*a.x; acc[1] += xv*a.y; acc[2] += xv*a.z; acc[3] += xv*a.w;
        acc[4] += xv*b.x; acc[5] += xv*b.y; acc[6] += xv*b.z; acc[7] += xv*b.w;
    }
    #pragma unroll
    for (int e = 0; e < NE; e++)
        #pragma unroll
        for (int o = 16; o > 0; o >>= 1) acc[e] += __shfl_xor_sync(0xFFFFFFFFu, acc[e], o);
    if (lane == 0) {
        float v[NE];
        #pragma unroll
        for (int e = 0; e < NE; e++) v[e] = acc[e] + gb[e];
        int i1 = 0;
        #pragma unroll
        for (int e = 1; e < NE; e++) if (v[e] > v[i1]) i1 = e;
        int i2 = (i1 == 0) ? 1 : 0;
        #pragma unroll
        for (int e = 0; e < NE; e++) if (e != i1 && v[e] > v[i2]) i2 = e;
        float e2 = expf(v[i2] - v[i1]);
        float s = 1.f + e2;
        int s1 = atomicAdd(&g_counts[i1], 1);
        g_tok[i1][s1] = warp; g_gate[i1][s1] = 1.f / s;
        int s2 = atomicAdd(&g_counts[i2], 1);
        g_tok[i2][s2] = warp; g_gate[i2][s2] = e2 / s;
    }
}

__global__ void gather_kernel(const float* __restrict__ x) {
    int e = blockIdx.y;
    int slot = blockIdx.x * 2 + (threadIdx.x >> 7);
    if (slot >= g_counts[e]) return;
    int tok = g_tok[e][slot];
    int row = g_base[e] + slot;
    int lane = threadIdx.x & 127;
    const float4* s = (const float4*)(x + (size_t)tok * DM);
    uint2* d = (uint2*)(g_Xgh + (size_t)row * DM);
    #pragma unroll
    for (int i = 0; i < 2; i++) {
        float4 v = s[lane + i * 128];
        __half2 h0 = __floats2half2_rn(v.x, v.y);
        __half2 h1 = __floats2half2_rn(v.z, v.w);
        uint2 o;
        o.x = *reinterpret_cast<uint32_t*>(&h0);
        o.y = *reinterpret_cast<uint32_t*>(&h1);
        d[lane + i * 128] = o;
    }
}

// fp32 -> fp16 conversion of BOTH weight tensors in one launch
__global__ void conv_half_kernel(const float4* __restrict__ s1, uint4* __restrict__ d1,
                                 const float4* __restrict__ s2, uint4* __restrict__ d2, int n8) {
    int i = blockIdx.x * blockDim.x + threadIdx.x;
    if (i >= 2 * n8) return;
    const float4* s = (i < n8) ? s1 : s2;
    uint4* d = (i < n8) ? d1 : d2;
    int j = (i < n8) ? i : (i - n8);
    float4 v0 = s[j * 2], v1 = s[j * 2 + 1];
    __half2 h0 = __floats2half2_rn(v0.x, v0.y);
    __half2 h1 = __floats2half2_rn(v0.z, v0.w);
    __half2 h2 = __floats2half2_rn(v1.x, v1.y);
    __half2 h3 = __floats2half2_rn(v1.z, v1.w);
    uint4 o;
    o.x = *reinterpret_cast<uint32_t*>(&h0);
    o.y = *reinterpret_cast<uint32_t*>(&h1);
    o.z = *reinterpret_cast<uint32_t*>(&h2);
    o.w = *reinterpret_cast<uint32_t*>(&h3);
    d[j] = o;
}

// ---------------- fp16 mma grouped GEMM ----------------
// CTA 128x256, 512 threads = 16 warps (2 x 8), warp tile 64x32, k-chunk 32.
// smem (halves): A [128][40], B [32][264], 4-stage pipeline.
#define ASTRH 40
#define BSTRH 264
#define ABUFB (128 * ASTRH * 2)          // 10240 B
#define BBUFB (32 * BSTRH * 2)           // 16896 B
#define BUFB  (ABUFB + BBUFB)            // 27136 B
#define NSTAGE 4
#define SMEM_DYN (NSTAGE * BUFB)         // 108544 B

template<int KDIM, int NDIM, bool GELU_OUT>
__global__ void __launch_bounds__(512, 1)
gemm_mma(const __half* __restrict__ Bmat, const float* __restrict__ bias,
         float* __restrict__ outp) {
    const int e = blockIdx.z;
    const int count = g_counts[e];
    const int m0 = blockIdx.x * 128;
    if (m0 >= count) return;
    const int base = g_base[e];
    const int n0 = blockIdx.y * 256;

    extern __shared__ char smraw[];
    const uint32_t su = smem_u32(smraw);

    const int tid  = threadIdx.x;
    const int wid  = tid >> 5;
    const int lane = tid & 31;
    const int g    = lane >> 2;
    const int tg   = lane & 3;
    const int wr   = wid & 1;    // 2 warp rows x 64
    const int wc   = wid >> 1;   // 8 warp cols x 32

    const __half* Asrc = (GELU_OUT ? g_Xgh : g_Hh) + (size_t)(base + m0) * KDIM;
    const __half* Bsrc = Bmat + (size_t)e * KDIM * NDIM + n0;

    // loader mapping (512 threads): A 128 rows x 4 chunks = 512 cp (1/thread)
    const int am = tid >> 2;
    const int ac = tid & 3;
    // B 32 rows x 32 chunks = 1024 cp (2/thread)
    const int bk = tid >> 4;
    const int bc = tid & 15;

    const int lane_r  = (lane & 7) + ((lane >> 3) & 1) * 8;
    const int lane_k8 = (lane >> 4) * 16;

    float c[4][4][4];
    #pragma unroll
    for (int i = 0; i < 4; i++)
        #pragma unroll
        for (int j = 0; j < 4; j++)
            #pragma unroll
            for (int k = 0; k < 4; k++) c[i][j][k] = 0.f;

    const int KC = KDIM / 32;

    #define LOAD_TILES(kc_, buf_) do { \
        uint32_t sa = su + (buf_) * BUFB; \
        uint32_t sb = sa + ABUFB; \
        const __half* asp = Asrc + (size_t)am * KDIM + (kc_) * 32; \
        CP_ASYNC16(sa + (uint32_t)(am * 80 + ac * 16), asp + ac * 8); \
        const __half* bsp = Bsrc + (size_t)((kc_) * 32 + bk) * NDIM; \
        CP_ASYNC16(sb + (uint32_t)(bk * 528 + bc * 16), bsp + bc * 8); \
        CP_ASYNC16(sb + (uint32_t)(bk * 528 + (bc + 16) * 16), bsp + (bc + 16) * 8); \
    } while (0)

    LOAD_TILES(0, 0); CP_COMMIT();
    LOAD_TILES(1, 1); CP_COMMIT();
    LOAD_TILES(2, 2); CP_COMMIT();

    for (int kc = 0; kc < KC; kc++) {
        CP_WAIT2();
        __syncthreads();
        if (kc + 3 < KC) LOAD_TILES(kc + 3, (kc + 3) & 3);
        CP_COMMIT();

        const uint32_t sa = su + (kc & 3) * BUFB;
        const uint32_t sb = sa + ABUFB;
        const uint32_t a_base = sa + (uint32_t)((wr * 64 + lane_r) * 80) + lane_k8;
        const uint32_t b_base = sb + (uint32_t)(lane_r * 528 + wc * 64) + lane_k8;

        #pragma unroll
        for (int ks = 0; ks < 2; ks++) {
            uint32_t a[4][4];
            #pragma unroll
            for (int mf = 0; mf < 4; mf++)
                LDMATRIX_X4(a[mf][0], a[mf][1], a[mf][2], a[mf][3],
                            a_base + mf * 1280 + ks * 32);
            uint32_t b[4][2];
            #pragma unroll
            for (int np = 0; np < 2; np++) {
                uint32_t r0, r1, r2, r3;
                LDMATRIX_X4_T(r0, r1, r2, r3, b_base + ks * 8448 + np * 32);
                b[np * 2 + 0][0] = r0; b[np * 2 + 0][1] = r1;
                b[np * 2 + 1][0] = r2; b[np * 2 + 1][1] = r3;
            }
            #pragma unroll
            for (int mf = 0; mf < 4; mf++)
                #pragma unroll
                for (int nf = 0; nf < 4; nf++)
                    MMA_F16(c[mf][nf], a[mf], b[nf][0], b[nf][1]);
        }
    }

    // -------- epilogue --------
    #pragma unroll
    for (int mf = 0; mf < 4; mf++) {
        #pragma unroll
        for (int half_ = 0; half_ < 2; half_++) {
            int rl = wr * 64 + mf * 16 + g + half_ * 8;
            int m = m0 + rl;
            if (m >= count) continue;
            if (GELU_OUT) {
                __half* hrow = g_Hh + (size_t)(base + m) * FFN_;
                #pragma unroll
                for (int nf = 0; nf < 4; nf++) {
                    int col = n0 + wc * 32 + nf * 8 + 2 * tg;
                    float2 bb = *(const float2*)(bias + (size_t)e * NDIM + col);
                    __half2 hv = __floats2half2_rn(
                        gelu_exact(c[mf][nf][half_ * 2 + 0] + bb.x),
                        gelu_exact(c[mf][nf][half_ * 2 + 1] + bb.y));
                    *reinterpret_cast<__half2*>(hrow + col) = hv;
                }
            } else {
                int tok = g_tok[e][m];
                float gt = g_gate[e][m];
                float* orow = outp + (size_t)tok * DM;
                #pragma unroll
                for (int nf = 0; nf < 4; nf++) {
                    int col = n0 + wc * 32 + nf * 8 + 2 * tg;
                    float2 bb = *(const float2*)(bias + (size_t)e * NDIM + col);
                    atomicAdd(orow + col + 0, gt * (c[mf][nf][half_ * 2 + 0] + bb.x));
                    atomicAdd(orow + col + 1, gt * (c[mf][nf][half_ * 2 + 1] + bb.y));
                }
            }
        }
    }
}

// ---------------- launch ----------------
extern "C" void kernel_launch(void* const* d_in, const int* in_sizes, int n_in,
                              void* d_out, int out_size) {
    const float* x  = (const float*)d_in[0];
    const float* gw = (const float*)d_in[1];
    const float* gb = (const float*)d_in[2];
    const float* w1 = (const float*)d_in[3];
    const float* b1 = (const float*)d_in[4];
    const float* w2 = (const float*)d_in[5];
    const float* b2 = (const float*)d_in[6];
    float* out = (float*)d_out;
    const int T = in_sizes[0] / DM;

    __half* w1h; cudaGetSymbolAddress((void**)&w1h, g_w1h);
    __half* w2h; cudaGetSymbolAddress((void**)&w2h, g_w2h);

    static int attr_done = 0;
    if (!attr_done) {
        cudaFuncSetAttribute(gemm_mma<DM, FFN_, true>,
                             cudaFuncAttributeMaxDynamicSharedMemorySize, SMEM_DYN);
        cudaFuncSetAttribute(gemm_mma<FFN_, DM, false>,
                             cudaFuncAttributeMaxDynamicSharedMemorySize, SMEM_DYN);
        attr_done = 1;
    }

    init_kernel<<<1, 32>>>();
    route_kernel<<<(T + 7) / 8, 256>>>(x, gw, gb, T);
    base_kernel<<<1, 32>>>();
    gather_kernel<<<dim3((T + 1) / 2, NE), 256>>>(x);

    const int n8 = NE * DM * FFN_ / 8;
    conv_half_kernel<<<(2 * n8 + 255) / 256, 256>>>(
        (const float4*)w1, (uint4*)w1h, (const float4*)w2, (uint4*)w2h, n8);

    cudaMemsetAsync(d_out, 0, (size_t)out_size * sizeof(float), 0);

    gemm_mma<DM, FFN_, true><<<dim3(T / 128, FFN_ / 256, NE), 512, SMEM_DYN>>>(w1h, b1, nullptr);
    gemm_mma<FFN_, DM, false><<<dim3(T / 128, DM / 256, NE), 512, SMEM_DYN>>>(w2h, b2, out);
}